// round 4
// baseline (speedup 1.0000x reference)
#include <cuda_runtime.h>
#include <cstdint>

// Problem constants
#define B_TOT 16384
#define T_SEQ 784
#define HID   30
#define NCLS  10
#define NJP   16   // 15 packed h-pairs + 1 slot for (x_t, 0)

typedef unsigned long long u64;

// ---- packed f32x2 helpers (Blackwell FFMA2 path, PTX-only) ----
__device__ __forceinline__ u64 pk2(float lo, float hi) {
    u64 r; asm("mov.b64 %0, {%1, %2};" : "=l"(r) : "f"(lo), "f"(hi)); return r;
}
__device__ __forceinline__ void upk2(float& lo, float& hi, u64 v) {
    asm("mov.b64 {%0, %1}, %2;" : "=f"(lo), "=f"(hi) : "l"(v));
}
__device__ __forceinline__ u64 ffma2(u64 a, u64 b, u64 c) {
    u64 d; asm("fma.rn.f32x2 %0, %1, %2, %3;" : "=l"(d) : "l"(a), "l"(b), "l"(c));
    return d;
}
__device__ __forceinline__ u64 fmul2(u64 a, u64 b) {
    u64 d; asm("mul.rn.f32x2 %0, %1, %2;" : "=l"(d) : "l"(a), "l"(b));
    return d;
}

// One thread = one batch element. h kept in registers as 15 packed f32x2
// pairs; z partials accumulated as f32x2 lane-pairs over the contraction dim,
// horizontally reduced per step. W table in SMEM, broadcast LDS.128.
__global__ void __launch_bounds__(128)
rnn_modrelu_kernel(const float* __restrict__ inputs,   // [B, 784]
                   const float* __restrict__ W_ih,     // [30, 1]
                   const float* __restrict__ W_hh,     // [30, 30] row-major: W_hh[i][j]
                   const float* __restrict__ b_mod,    // [30]
                   const float* __restrict__ W_lin,    // [10, 30]
                   const float* __restrict__ b_lin,    // [10]
                   float* __restrict__ out)            // [B, 10]
{
    // w2s[jp][i] = packed (W_hh[i][2jp], W_hh[i][2jp+1]) for jp<15
    // w2s[15][i] = packed (W_ih[i], 0)   -- x_t folded in as a 16th pair
    // Row length 30*8 = 240 B (16B-multiple) so ulonglong2 loads are aligned.
    __shared__ __align__(16) u64 w2s[NJP][HID];
    __shared__ float bms[HID];

    const int tid = threadIdx.x;
    for (int idx = tid; idx < NJP * HID; idx += blockDim.x) {
        const int jp = idx / HID, i = idx % HID;
        float lo, hi;
        if (jp < 15) { lo = W_hh[i * HID + 2 * jp]; hi = W_hh[i * HID + 2 * jp + 1]; }
        else         { lo = W_ih[i];                hi = 0.0f; }
        w2s[jp][i] = pk2(lo, hi);
    }
    if (tid < HID) bms[tid] = b_mod[tid];
    __syncthreads();

    float bm[HID];
#pragma unroll
    for (int i = 0; i < HID; i++) bm[i] = bms[i];

    const int b = blockIdx.x * 128 + tid;
    const float2* __restrict__ xrow =
        reinterpret_cast<const float2*>(inputs + (size_t)b * T_SEQ);

    u64 hp[NJP];
#pragma unroll
    for (int jp = 0; jp < NJP; jp++) hp[jp] = 0ull;

    float2 xv = __ldg(&xrow[0]);
    const int NIT = T_SEQ / 2;  // 392
    for (int t2 = 0; t2 < NIT; ++t2) {
        // prefetch next pair of pixels (clamped, uniform across the warp)
        const unsigned nidx = min((unsigned)(t2 + 1), (unsigned)(NIT - 1));
        float2 xn = __ldg(&xrow[nidx]);

#pragma unroll
        for (int s = 0; s < 2; s++) {
            const float x = s ? xv.y : xv.x;
            hp[15] = pk2(x, 0.0f);

            u64 acc[HID];
            // jp = 0 initializes accumulators (saves 30 zero-movs)
            {
                const ulonglong2* __restrict__ wrow =
                    reinterpret_cast<const ulonglong2*>(&w2s[0][0]);
#pragma unroll
                for (int i2 = 0; i2 < 15; i2++) {
                    ulonglong2 w = wrow[i2];
                    acc[2 * i2]     = fmul2(w.x, hp[0]);
                    acc[2 * i2 + 1] = fmul2(w.y, hp[0]);
                }
            }
#pragma unroll
            for (int jp = 1; jp < NJP; jp++) {
                const ulonglong2* __restrict__ wrow =
                    reinterpret_cast<const ulonglong2*>(&w2s[jp][0]);
#pragma unroll
                for (int i2 = 0; i2 < 15; i2++) {
                    ulonglong2 w = wrow[i2];
                    acc[2 * i2]     = ffma2(w.x, hp[jp], acc[2 * i2]);
                    acc[2 * i2 + 1] = ffma2(w.y, hp[jp], acc[2 * i2 + 1]);
                }
            }

            // horizontal reduce + modReLU:  h = copysign(max(|z|+b, 0), z)
            float hnew[HID];
#pragma unroll
            for (int i = 0; i < HID; i++) {
                float lo, hi;
                upk2(lo, hi, acc[i]);
                const float z = lo + hi;
                const float m = fmaxf(fabsf(z) + bm[i], 0.0f);
                hnew[i] = copysignf(m, z);
            }
#pragma unroll
            for (int jp = 0; jp < 15; jp++)
                hp[jp] = pk2(hnew[2 * jp], hnew[2 * jp + 1]);
        }
        xv = xn;
    }

    // Linear head: out[b][c] = b_lin[c] + sum_i W_lin[c][i] * h[i]
    float h[HID];
#pragma unroll
    for (int jp = 0; jp < 15; jp++) upk2(h[2 * jp], h[2 * jp + 1], hp[jp]);

#pragma unroll
    for (int c = 0; c < NCLS; c++) {
        float a = __ldg(&b_lin[c]);
#pragma unroll
        for (int i = 0; i < HID; i++)
            a = fmaf(__ldg(&W_lin[c * HID + i]), h[i], a);
        out[(size_t)b * NCLS + c] = a;
    }
}

extern "C" void kernel_launch(void* const* d_in, const int* in_sizes, int n_in,
                              void* d_out, int out_size) {
    const float* inputs = (const float*)d_in[0];
    const float* W_ih   = (const float*)d_in[1];
    const float* W_hh   = (const float*)d_in[2];
    const float* b_mod  = (const float*)d_in[3];
    const float* W_lin  = (const float*)d_in[4];
    const float* b_lin  = (const float*)d_in[5];
    float* out = (float*)d_out;

    rnn_modrelu_kernel<<<B_TOT / 128, 128>>>(inputs, W_ih, W_hh, b_mod,
                                             W_lin, b_lin, out);
}